// round 8
// baseline (speedup 1.0000x reference)
#include <cuda_runtime.h>
#include <cuda_bf16.h>

// StixelLoss v8: fine-grain blocks (b,c,w-quarter), full-column register scan,
// batched scalar loads with immediate offsets, single-kernel reduction.
// inputs:  (B=256, C=2, H=192, W=256) f32 in (1e-4, 1-1e-4)
// targets: (1, B, C, H, W) f32
// out:     scalar f32 = 1.0*bce_mean + 0.001*cuts + 0.1*dense

#define HH    192
#define WW    256
#define NBC   512
#define WQ    4                  // W quarters
#define NBLK  (NBC * WQ)         // 2048 blocks
#define NTHR  64                 // one thread per column in the quarter

__device__ float    g_acc = 0.0f;
__device__ unsigned g_cnt = 0u;

__global__ __launch_bounds__(NTHR)
void stixel_kernel(const float* __restrict__ inp,
                   const float* __restrict__ tgt,
                   float* __restrict__ out) {
    const int bc = blockIdx.x >> 2;          // b*2 + c
    const int wq = blockIdx.x & 3;           // W quarter
    const int c  = bc & 1;
    const int col = wq * NTHR + threadIdx.x;

    const float* gp = inp + (size_t)bc * (HH * WW) + col;
    const float* gt = tgt + (size_t)bc * (HH * WW) + col;

    float bce   = 0.0f;
    float dense = 0.0f;
    int   cuts  = 0;
    int   prev  = -1;            // -1 = no visible predecessor

    #pragma unroll
    for (int w = 0; w < 6; ++w) {            // 6 words x 32 rows
        unsigned curw = 0;
        #pragma unroll
        for (int half = 0; half < 2; ++half) {
            float pv[16], tv[16];
            // batched loads, compile-time offsets (immediate-form LDG)
            #pragma unroll
            for (int i = 0; i < 16; ++i) {
                const int h = w * 32 + half * 16 + i;
                pv[i] = gp[h * WW];
                tv[i] = gt[h * WW];
            }
            #pragma unroll
            for (int i = 0; i < 16; ++i) {
                float lp  = __log2f(pv[i]);
                float l1p = __log2f(1.0f - pv[i]);
                bce += l1p + tv[i] * (lp - l1p);
                if (pv[i] > 0.5f) curw |= (1u << (half * 16 + i));
            }
        }

        if (c == 0) {
            cuts += __popc(curw);            // all 192 rows of channel 0 count
        } else {
            // dense scan. Reference semantics:
            //  - hit at h=0 invisible (prev!=0 gate)  -> clear bit 0
            //  - h=191 excluded (loop runs h<H-1)     -> clear bit 31 of word 5
            unsigned wb = curw;
            if (w == 0) wb &= ~1u;
            if (w == 5) wb &= 0x7fffffffu;
            const int base = w * 32;
            while (wb) {
                int b = __ffs(wb) - 1;
                wb &= (wb - 1);
                int pos = base + b;
                if (prev >= 0) {
                    float d = (float)(pos - prev);
                    dense += __fdividef(1.0f, d * d * d);
                }
                prev = pos;
            }
        }
    }

    // combine (ALPHA=1, BETA=0.001, GAMMA=0.1); bce is in log2 units
    const float SCALE_BCE = -0.69314718055994531f /
                            (float)((size_t)NBC * HH * WW);
    float val = bce * SCALE_BCE + 0.001f * (float)cuts + 0.1f * dense;

    // block reduction over 64 threads (2 warps)
    __shared__ float sred[2];
    #pragma unroll
    for (int off = 16; off > 0; off >>= 1)
        val += __shfl_down_sync(0xffffffffu, val, off);
    const int lane = threadIdx.x & 31;
    const int wid  = threadIdx.x >> 5;
    if (lane == 0) sred[wid] = val;
    __syncthreads();

    if (threadIdx.x == 0) {
        float bsum = sred[0] + sred[1];
        atomicAdd(&g_acc, bsum);
        __threadfence();
        unsigned old = atomicAdd(&g_cnt, 1u);
        if (old == NBLK - 1) {
            // last block: publish result, reset scratch for the next replay
            float total = atomicAdd(&g_acc, 0.0f);   // L2-coherent read
            out[0] = total;
            __threadfence();
            g_acc = 0.0f;
            g_cnt = 0u;
        }
    }
}

extern "C" void kernel_launch(void* const* d_in, const int* in_sizes, int n_in,
                              void* d_out, int out_size) {
    const float* inp = (const float*)d_in[0];
    const float* tgt = (const float*)d_in[1];
    float* out = (float*)d_out;

    stixel_kernel<<<NBLK, NTHR>>>(inp, tgt, out);
}

// round 9
// speedup vs baseline: 1.4904x; 1.4904x over previous
#include <cuda_runtime.h>
#include <cuda_bf16.h>

// StixelLoss v9: R5 engine (float4 + bitmask + log2), W-halved blocks for
// single-wave residency, single-kernel last-block reduction.
// inputs:  (B=256, C=2, H=192, W=256) f32 in (1e-4, 1-1e-4)
// targets: (1, B, C, H, W) f32
// out:     scalar f32 = 1.0*bce_mean + 0.001*cuts + 0.1*dense

#define HH    192
#define WW    256
#define NBC   512
#define NBLK  (NBC * 2)       // 1024 blocks: (b, c, w-half)
#define WH    128             // columns per block
#define NQ    32              // float4 quads per block row
#define NSEG  8               // 24-row segments
#define SEGH  24
#define TABN  1216            // 1/d^3 lookup incl. sentinel fold
#define SENT  (-1000)         // prev sentinel: pos-SENT in [1001,1190] -> tab 0

__device__ float    g_acc = 0.0f;
__device__ unsigned g_cnt = 0u;

__global__ __launch_bounds__(256, 8)
void stixel_kernel(const float* __restrict__ inp,
                   const float* __restrict__ tgt,
                   float* __restrict__ out) {
    const int bc = blockIdx.x >> 1;          // b*2 + c
    const int wh = blockIdx.x & 1;           // w-half
    const int c  = bc & 1;
    const int q  = threadIdx.x & (NQ - 1);   // quad (cols 4q..4q+3 in half)
    const int s  = threadIdx.x >> 5;         // h-segment 0..7
    const int h0 = s * SEGH;

    __shared__ float        tab[TABN];
    __shared__ unsigned int smask[NSEG][WH];
    __shared__ float        sred[8];

    // channel-1 blocks: fill 1/d^3 table (zero outside [1,190])
    if (c == 1) {
        for (int k = threadIdx.x; k < TABN; k += 256) {
            float fd = (float)k;
            tab[k] = (k >= 1 && k < HH - 1) ? (1.0f / (fd * fd * fd)) : 0.0f;
        }
    }

    const size_t base = (size_t)bc * (HH * WW) + (size_t)h0 * WW
                      + (size_t)wh * WH + 4 * q;
    const float4* ip4 = (const float4*)(inp + base);
    const float4* tp4 = (const float4*)(tgt + base);

    float bce = 0.0f;
    unsigned int m0 = 0, m1 = 0, m2 = 0, m3 = 0;

    // hot loop (identical both channels): log2-domain BCE + mask build
    #pragma unroll
    for (int i = 0; i < SEGH; ++i) {
        float4 p = ip4[i * (WW / 4)];
        float4 t = tp4[i * (WW / 4)];
        {
            float lp = __log2f(p.x), l1p = __log2f(1.0f - p.x);
            bce += l1p + t.x * (lp - l1p);
            if (p.x > 0.5f) m0 |= (1u << i);
        }
        {
            float lp = __log2f(p.y), l1p = __log2f(1.0f - p.y);
            bce += l1p + t.y * (lp - l1p);
            if (p.y > 0.5f) m1 |= (1u << i);
        }
        {
            float lp = __log2f(p.z), l1p = __log2f(1.0f - p.z);
            bce += l1p + t.z * (lp - l1p);
            if (p.z > 0.5f) m2 |= (1u << i);
        }
        {
            float lp = __log2f(p.w), l1p = __log2f(1.0f - p.w);
            bce += l1p + t.w * (lp - l1p);
            if (p.w > 0.5f) m3 |= (1u << i);
        }
    }

    float dense = 0.0f;
    int   cuts  = 0;

    if (c == 0) {
        cuts = __popc(m0) + __popc(m1) + __popc(m2) + __popc(m3);
    } else {
        smask[s][4 * q + 0] = m0;
        smask[s][4 * q + 1] = m1;
        smask[s][4 * q + 2] = m2;
        smask[s][4 * q + 3] = m3;
        __syncthreads();

        const int col  = threadIdx.x & (WH - 1);
        const int half = threadIdx.x >> 7;   // 0: rows 0..95, 1: rows 96..191

        int prev = SENT;
        if (half == 1) {
            // initial prev = last hit in rows 0..95 (bit 0 of seg0 invisible)
            unsigned int u3 = smask[3][col];
            unsigned int u2 = smask[2][col];
            unsigned int u1 = smask[1][col];
            unsigned int u0 = smask[0][col] & ~1u;
            if      (u3) prev = 72 + 31 - __clz(u3);
            else if (u2) prev = 48 + 31 - __clz(u2);
            else if (u1) prev = 24 + 31 - __clz(u1);
            else if (u0) prev =      31 - __clz(u0);
        }

        #pragma unroll
        for (int k = 0; k < 4; ++k) {
            unsigned int w = smask[half * 4 + k][col];
            if (half == 0 && k == 0) w &= ~1u;          // h=0 hit invisible
            if (half == 1 && k == 3) w &= ~(1u << 23);  // h=191 excluded
            const int rowbase = (half * 4 + k) * SEGH;
            while (w) {
                int b = __ffs(w) - 1;
                w &= (w - 1);
                int pos = rowbase + b;
                dense += tab[pos - prev];   // tab==0 when prev is sentinel
                prev = pos;
            }
        }
    }

    // combine (ALPHA=1, BETA=0.001, GAMMA=0.1); bce is in log2 units
    const float SCALE_BCE = -0.69314718055994531f /
                            (float)((size_t)NBC * HH * WW);
    float val = bce * SCALE_BCE + 0.001f * (float)cuts + 0.1f * dense;

    // block reduction over 256 threads
    #pragma unroll
    for (int off = 16; off > 0; off >>= 1)
        val += __shfl_down_sync(0xffffffffu, val, off);
    const int lane = threadIdx.x & 31;
    const int wid  = threadIdx.x >> 5;
    if (lane == 0) sred[wid] = val;
    __syncthreads();

    if (wid == 0) {
        val = (lane < 8) ? sred[lane] : 0.0f;
        #pragma unroll
        for (int off = 4; off > 0; off >>= 1)
            val += __shfl_down_sync(0xffffffffu, val, off);
        if (lane == 0) {
            atomicAdd(&g_acc, val);
            __threadfence();
            unsigned old = atomicAdd(&g_cnt, 1u);
            if (old == NBLK - 1) {
                // last block: publish result, reset scratch for next replay
                float total = atomicAdd(&g_acc, 0.0f);  // coherent read
                out[0] = total;
                __threadfence();
                g_acc = 0.0f;
                g_cnt = 0u;
            }
        }
    }
}

extern "C" void kernel_launch(void* const* d_in, const int* in_sizes, int n_in,
                              void* d_out, int out_size) {
    const float* inp = (const float*)d_in[0];
    const float* tgt = (const float*)d_in[1];
    float* out = (float*)d_out;

    stixel_kernel<<<NBLK, 256>>>(inp, tgt, out);
}